// round 15
// baseline (speedup 1.0000x reference)
#include <cuda_runtime.h>
#include <math.h>
#include <stdint.h>

#define BATCH   1024
#define IN_DIM  256
#define NG      512
#define OUT_DIM 256
#define CAP     2048.0f
#define SLOTS   16

__device__ __align__(16) float g_gauss[BATCH * NG];

__device__ __forceinline__ uint32_t fbits(float f) { return __float_as_uint(f); }

__device__ __forceinline__ void mma_tf32(float d[4],
    uint32_t a0, uint32_t a1, uint32_t a2, uint32_t a3,
    uint32_t b0, uint32_t b1) {
    asm volatile(
        "mma.sync.aligned.m16n8k8.row.col.f32.tf32.tf32.f32 "
        "{%0,%1,%2,%3}, {%4,%5,%6,%7}, {%8,%9}, {%0,%1,%2,%3};\n"
        : "+f"(d[0]), "+f"(d[1]), "+f"(d[2]), "+f"(d[3])
        : "r"(a0), "r"(a1), "r"(a2), "r"(a3), "r"(b0), "r"(b1));
}

__device__ __forceinline__ void cp16(void* smem_dst, const void* gsrc) {
    uint32_t s = (uint32_t)__cvta_generic_to_shared(smem_dst);
    asm volatile("cp.async.cg.shared.global [%0], [%1], 16;\n" :: "r"(s), "l"(gsrc));
}
__device__ __forceinline__ void cp_commit() {
    asm volatile("cp.async.commit_group;\n");
}
template <int N>
__device__ __forceinline__ void cp_wait() {
    asm volatile("cp.async.wait_group %0;\n" :: "n"(N));
}

// ============================================================================
// GEMM1 v6: tile 32(m) x 32(g), grid 512 CTAs -> 2 CTAs/SM (4 warps/SMSP).
// Same fused-prep + smem-resident barrier-free mainloop as before.
// 8 warps as 2m x 4n, warp tile 16m x 8g.
// ============================================================================
#define B_ST 260
#define XS_OFF 0                          // 32*256 = 8192
#define B1_OFF 8192                       // 32*260 = 8320
#define B2_OFF (B1_OFF + 32 * B_ST)       // 16512
#define BS_OFF (B2_OFF + 32 * B_ST)       // 24832 (+32)
#define CN_OFF (BS_OFF + 32)              // (+32)
#define LE_OFF (CN_OFF + 32)              // 32*SLOTS
#define LC_OFF (LE_OFF + 32 * SLOTS)
#define LK_OFF (LC_OFF + 32 * SLOTS)
#define SMEM_FLOATS (LK_OFF + 32 * SLOTS)
#define SMEM_BYTES (SMEM_FLOATS * 4)      // ~105.3 KB -> 2 CTAs/SM

__global__ void __launch_bounds__(256, 2)
gemm1_kernel(const float* __restrict__ x,
             const float* __restrict__ centers,
             const float* __restrict__ stds) {
    extern __shared__ float sm[];
    float* Xs    = sm + XS_OFF;
    float* B1s   = sm + B1_OFF;
    float* B2s   = sm + B2_OFF;
    float* biasS = sm + BS_OFF;
    int*   cntS  = (int*)(sm + CN_OFF);
    float* leS   = sm + LE_OFF;
    float* lcS   = sm + LC_OFF;
    int*   lkS   = (int*)(sm + LK_OFF);

    const int tid  = threadIdx.x;
    const int lane = tid & 31;
    const int qr   = lane >> 2;         // 0..7
    const int ql   = lane & 3;          // 0..3
    const int w    = tid >> 5;
    const int wm   = (w >> 2) * 16;     // 0,16
    const int wn   = (w & 3) * 8;       // 0,8,16,24
    const int m0   = blockIdx.y * 32;
    const int n0   = blockIdx.x * 32;
    const int swzf = qr << 2;

    // ---- staging: 8 threads per row (lr = tid>>3, e = tid&7) ----
    const int lr   = tid >> 3;          // 0..31 (row / gaussian)
    const int e    = tid & 7;           // 0..7
    const int swzl = (lr & 7) << 2;
    const unsigned FULL = 0xffffffffu;

    float bias_part = 0.f;
    int   base      = 0;
    #pragma unroll 2
    for (int it = 0; it < 8; ++it) {
        const int k0 = it * 32 + e * 4;
        float4 xv = *(const float4*)&x[(m0 + lr) * IN_DIM + k0];
        *(float4*)&Xs[lr * 256 + (k0 ^ swzl)] = xv;

        float4 cv = *(const float4*)&centers[(n0 + lr) * IN_DIM + k0];
        float4 sv = *(const float4*)&stds   [(n0 + lr) * IN_DIM + k0];
        float cc[4] = {cv.x, cv.y, cv.z, cv.w};
        float inv[4];
        inv[0] = 1.f / (sv.x * sv.x); inv[1] = 1.f / (sv.y * sv.y);
        inv[2] = 1.f / (sv.z * sv.z); inv[3] = 1.f / (sv.w * sv.w);
        float ic[4];
        ic[0] = fminf(inv[0], CAP); ic[1] = fminf(inv[1], CAP);
        ic[2] = fminf(inv[2], CAP); ic[3] = fminf(inv[3], CAP);
        float4 b1v = make_float4(cc[0]*ic[0], cc[1]*ic[1], cc[2]*ic[2], cc[3]*ic[3]);
        float4 b2v = make_float4(-0.5f*ic[0], -0.5f*ic[1], -0.5f*ic[2], -0.5f*ic[3]);
        *(float4*)&B1s[lr * B_ST + k0] = b1v;
        *(float4*)&B2s[lr * B_ST + k0] = b2v;
        bias_part -= 0.5f * (cc[0]*cc[0]*ic[0] + cc[1]*cc[1]*ic[1] +
                             cc[2]*cc[2]*ic[2] + cc[3]*cc[3]*ic[3]);

        // excess compaction within the 8-lane segment (deterministic order)
        unsigned m = (inv[0] > CAP ? 1u : 0u) | (inv[1] > CAP ? 2u : 0u) |
                     (inv[2] > CAP ? 4u : 0u) | (inv[3] > CAP ? 8u : 0u);
        int cnt  = __popc(m);
        int incl = cnt;
        #pragma unroll
        for (int off = 1; off < 8; off <<= 1) {
            int t = __shfl_up_sync(FULL, incl, off, 8);
            if (e >= off) incl += t;
        }
        int slot  = base + (incl - cnt);
        int total = __shfl_sync(FULL, incl, 7, 8);
        #pragma unroll
        for (int b = 0; b < 4; ++b) {
            if ((m >> b) & 1u) {
                if (slot < SLOTS) {
                    leS[lr * SLOTS + slot] = -0.5f * (inv[b] - CAP);
                    lcS[lr * SLOTS + slot] = cc[b];
                    lkS[lr * SLOTS + slot] = k0 + b;
                }
                slot++;
            }
        }
        base += total;
    }
    bias_part += __shfl_xor_sync(FULL, bias_part, 1);
    bias_part += __shfl_xor_sync(FULL, bias_part, 2);
    bias_part += __shfl_xor_sync(FULL, bias_part, 4);
    if (e == 0) {
        biasS[lr] = bias_part;
        cntS[lr]  = base < SLOTS ? base : SLOTS;
    }
    __syncthreads();   // the ONLY barrier

    // ---- mainloop: warp tile 16m x 8g, pure LDS + HMMA ----
    float acc[4] = {};

    #pragma unroll 4
    for (int it = 0; it < 16; ++it) {
        #pragma unroll
        for (int ks = 0; ks < 16; ks += 8) {
            const int kb  = it * 16 + ks;
            const int kc0 = (kb + ql)     ^ swzf;
            const int kc1 = (kb + ql + 4) ^ swzf;
            const int r0  = (wm + qr) * 256;
            float f0 = Xs[r0 + kc0];
            float f1 = Xs[r0 + 2048 + kc0];
            float f2 = Xs[r0 + kc1];
            float f3 = Xs[r0 + 2048 + kc1];
            const int nb = (wn + qr) * B_ST + kb;
            uint32_t b10 = fbits(B1s[nb + ql]);
            uint32_t b11 = fbits(B1s[nb + ql + 4]);
            uint32_t b20 = fbits(B2s[nb + ql]);
            uint32_t b21 = fbits(B2s[nb + ql + 4]);
            mma_tf32(acc, fbits(f0), fbits(f1), fbits(f2), fbits(f3), b10, b11);
            mma_tf32(acc, fbits(f0*f0), fbits(f1*f1), fbits(f2*f2), fbits(f3*f3), b20, b21);
        }
    }

    // ---- sparse excess correction ----
    float corr[2][2];
    #pragma unroll
    for (int gi = 0; gi < 2; ++gi) {
        const int g   = wn + 2 * ql + gi;
        const int cnt = cntS[g];
        float c0 = 0.f, c1 = 0.f;
        for (int j = 0; j < cnt; ++j) {
            float ee = leS[g * SLOTS + j];
            float cc = lcS[g * SLOTS + j];
            int   kx = lkS[g * SLOTS + j] ^ swzf;
            float d0 = Xs[(wm     + qr) * 256 + kx] - cc;
            float d1 = Xs[(wm + 8 + qr) * 256 + kx] - cc;
            c0 += ee * d0 * d0; c1 += ee * d1 * d1;
        }
        corr[gi][0] = c0; corr[gi][1] = c1;
    }

    // ---- epilogue ----
    const int mrow = m0 + wm + qr;
    const int ncol = wn + 2 * ql;
    const float b0 = biasS[ncol], b1 = biasS[ncol + 1];
    float2 e0, e1;
    e0.x = __expf(acc[0] + b0 + corr[0][0]);
    e0.y = __expf(acc[1] + b1 + corr[1][0]);
    e1.x = __expf(acc[2] + b0 + corr[0][1]);
    e1.y = __expf(acc[3] + b1 + corr[1][1]);
    *(float2*)&g_gauss[ mrow      * NG + n0 + ncol] = e0;
    *(float2*)&g_gauss[(mrow + 8) * NG + n0 + ncol] = e1;
}

// ============================================================================
// GEMM2 v6: tile 32(m) x 32(n), grid 256 CTAs -> 2+ CTAs/SM.
// 3-stage cp.async pipeline, BK=64. 8 warps as 2m x 4n, warp tile 16x8.
// ============================================================================
#define G2A_ST 68    // 64+4: A fragment banks 4*qr+ql, conflict-free
#define G2B_ST 40    // 32+8: B fragment banks 8*ql+qr+wn, conflict-free
#define G2_STAGES 3
#define G2A_OFF 0                                  // 3*32*68 = 6528
#define G2B_OFF (G2_STAGES * 32 * G2A_ST)          // 3*64*40 = 7680
#define G2_SMEM_FLOATS (G2B_OFF + G2_STAGES * 64 * G2B_ST)
#define G2_SMEM_BYTES (G2_SMEM_FLOATS * 4)         // ~56.8 KB

__global__ void __launch_bounds__(256, 2)
gemm2_kernel(const float* __restrict__ W, float* __restrict__ out) {
    extern __shared__ float sm2[];
    float* As = sm2 + G2A_OFF;   // [stage][32][G2A_ST]
    float* Bs = sm2 + G2B_OFF;   // [stage][64][G2B_ST]

    const int tid  = threadIdx.x;
    const int lane = tid & 31;
    const int qr   = lane >> 2;
    const int ql   = lane & 3;
    const int w    = tid >> 5;
    const int wm   = (w >> 2) * 16;   // 0,16
    const int wn   = (w & 3) * 8;     // 0,8,16,24
    const int m0   = blockIdx.y * 32;
    const int n0   = blockIdx.x * 32;

    // loader mapping: 2 float4 per thread per stage for each of A and B
    const int arow = tid >> 4;        // 0..15  (A rows, two passes)
    const int ac4  = (tid & 15) * 4;  // 0..60
    const int bkr  = tid >> 3;        // 0..31  (B k-rows, two passes)
    const int bn4  = (tid & 7) * 4;   // 0..28

    auto issue_stage = [&](int s, int it) {
        const int k0 = it * 64;
        cp16(&As[s * 32 * G2A_ST + arow * G2A_ST + ac4],
             &g_gauss[(m0 + arow) * NG + k0 + ac4]);
        cp16(&As[s * 32 * G2A_ST + (arow + 16) * G2A_ST + ac4],
             &g_gauss[(m0 + arow + 16) * NG + k0 + ac4]);
        cp16(&Bs[s * 64 * G2B_ST + bkr * G2B_ST + bn4],
             &W[(k0 + bkr) * OUT_DIM + n0 + bn4]);
        cp16(&Bs[s * 64 * G2B_ST + (bkr + 32) * G2B_ST + bn4],
             &W[(k0 + bkr + 32) * OUT_DIM + n0 + bn4]);
        cp_commit();
    };

    issue_stage(0, 0);
    issue_stage(1, 1);

    float acc[4] = {};

    #pragma unroll 2
    for (int it = 0; it < 8; ++it) {
        const int buf = it % G2_STAGES;
        cp_wait<1>();
        __syncthreads();

        const float* Ab = As + buf * 32 * G2A_ST;
        const float* Bb = Bs + buf * 64 * G2B_ST;
        #pragma unroll
        for (int ks = 0; ks < 64; ks += 8) {
            const int ar = (wm + qr) * G2A_ST + ks;
            uint32_t a0 = fbits(Ab[ar + ql]);
            uint32_t a1 = fbits(Ab[ar + 8 * G2A_ST + ql]);
            uint32_t a2 = fbits(Ab[ar + ql + 4]);
            uint32_t a3 = fbits(Ab[ar + 8 * G2A_ST + ql + 4]);
            uint32_t b0 = fbits(Bb[(ks + ql    ) * G2B_ST + wn + qr]);
            uint32_t b1 = fbits(Bb[(ks + ql + 4) * G2B_ST + wn + qr]);
            mma_tf32(acc, a0, a1, a2, a3, b0, b1);
        }
        if (it + 2 < 8) issue_stage((it + 2) % G2_STAGES, it + 2);
        else cp_commit();   // keep group count in sync for cp_wait<1>
    }

    const int mrow = m0 + wm + qr;
    const int ncol = n0 + wn + 2 * ql;
    *(float2*)&out[ mrow      * OUT_DIM + ncol] = make_float2(acc[0], acc[1]);
    *(float2*)&out[(mrow + 8) * OUT_DIM + ncol] = make_float2(acc[2], acc[3]);
}

extern "C" void kernel_launch(void* const* d_in, const int* in_sizes, int n_in,
                              void* d_out, int out_size) {
    const float* x       = (const float*)d_in[0];
    const float* centers = (const float*)d_in[1];
    const float* stds    = (const float*)d_in[2];
    const float* weights = (const float*)d_in[3];
    float* out = (float*)d_out;

    static int configured = 0;
    if (!configured) {
        cudaFuncSetAttribute(gemm1_kernel,
                             cudaFuncAttributeMaxDynamicSharedMemorySize, SMEM_BYTES);
        cudaFuncSetAttribute(gemm2_kernel,
                             cudaFuncAttributeMaxDynamicSharedMemorySize, G2_SMEM_BYTES);
        configured = 1;
    }

    gemm1_kernel<<<dim3(NG / 32, BATCH / 32), 256, SMEM_BYTES>>>(x, centers, stds);
    gemm2_kernel<<<dim3(OUT_DIM / 32, BATCH / 32), 256, G2_SMEM_BYTES>>>(weights, out);
}